// round 1
// baseline (speedup 1.0000x reference)
#include <cuda_runtime.h>
#include <cstdint>

#define NN    50000
#define EE    250000
#define INF_  9
#define OUTF  84
#define CH4   (OUTF/4)   // 21 float4 chunks per node row
#define EPS   1e-5f

// Scratch (static device globals; no allocation at runtime)
__device__ __align__(16) float g_u[NN * OUTF];     // x @ W   (W = nn_w row reshaped [9,84])
__device__ __align__(16) float g_v[NN * OUTF];     // x @ B   (B = nn_b reshaped [9,84])
__device__ __align__(16) float g_pre[NN * OUTF];   // x@root + bias, then += scatter-add(msg)
__device__ float g_stats[2 * OUTF];                // column sum, sumsq
__device__ int   g_is64;                           // edge_index dtype flag

// ---------------------------------------------------------------------------
// Detect whether edge_index is int64 or int32: if int64 (little-endian),
// the high dword of every element is 0 (indices < 2^31). Check 64 odd dwords.
__global__ void detect_kernel(const int* __restrict__ ei32) {
    if (threadIdx.x == 0 && blockIdx.x == 0) {
        int acc = 0;
        #pragma unroll
        for (int k = 0; k < 64; k++) acc |= ei32[2 * k + 1];
        g_is64 = (acc == 0) ? 1 : 0;
    }
}

// ---------------------------------------------------------------------------
// Kernel A: per-(node, out) precompute of u, v, pre. Also zero stats.
__global__ void prep_kernel(const float* __restrict__ x,
                            const float* __restrict__ nn_w,
                            const float* __restrict__ nn_b,
                            const float* __restrict__ root,
                            const float* __restrict__ bias) {
    int idx = blockIdx.x * blockDim.x + threadIdx.x;
    if (idx < 2 * OUTF) g_stats[idx] = 0.0f;
    if (idx >= NN * OUTF) return;
    int n = idx / OUTF;
    int o = idx - n * OUTF;

    float xr[INF_];
    #pragma unroll
    for (int i = 0; i < INF_; i++) xr[i] = x[n * INF_ + i];

    float u = 0.f, v = 0.f, p = bias[o];
    #pragma unroll
    for (int i = 0; i < INF_; i++) {
        u = fmaf(xr[i], nn_w[i * OUTF + o], u);
        v = fmaf(xr[i], nn_b[i * OUTF + o], v);
        p = fmaf(xr[i], root[i * OUTF + o], p);
    }
    g_u[idx] = u;
    g_v[idx] = v;
    g_pre[idx] = p;
}

// ---------------------------------------------------------------------------
// Kernel B: one thread per (edge, float4 chunk). msg = a*u[src] + v[src],
// vectorized L2 reduction into pre[dst].
__global__ void edge_kernel(const void* __restrict__ ei_raw,
                            const float* __restrict__ ea) {
    long long t = (long long)blockIdx.x * blockDim.x + threadIdx.x;
    if (t >= (long long)EE * CH4) return;
    int e = (int)(t / CH4);
    int c = (int)(t - (long long)e * CH4);

    int src, dst;
    if (g_is64) {
        const long long* ei = (const long long*)ei_raw;
        src = (int)ei[e];
        dst = (int)ei[EE + e];
    } else {
        const int* ei = (const int*)ei_raw;
        src = ei[e];
        dst = ei[EE + e];
    }
    float a = ea[e];

    const float4 u4 = *(const float4*)(g_u + (long long)src * OUTF + c * 4);
    const float4 v4 = *(const float4*)(g_v + (long long)src * OUTF + c * 4);
    float4 m;
    m.x = fmaf(a, u4.x, v4.x);
    m.y = fmaf(a, u4.y, v4.y);
    m.z = fmaf(a, u4.z, v4.z);
    m.w = fmaf(a, u4.w, v4.w);

    float* dptr = g_pre + (long long)dst * OUTF + c * 4;
    asm volatile("red.global.add.v4.f32 [%0], {%1, %2, %3, %4};"
                 :: "l"(dptr), "f"(m.x), "f"(m.y), "f"(m.z), "f"(m.w)
                 : "memory");
}

// ---------------------------------------------------------------------------
// Kernel C: column sums / sums-of-squares over g_pre. blockDim = 672 = 84*8:
// coalesced row-tile loads, shared tree reduce, one global atomic per column.
__global__ void stats_kernel() {
    const int col  = threadIdx.x % OUTF;
    const int rsub = threadIdx.x / OUTF;   // 0..7
    float s = 0.f, q = 0.f;
    for (int row = blockIdx.x * 8 + rsub; row < NN; row += gridDim.x * 8) {
        float v = g_pre[row * OUTF + col];
        s += v;
        q = fmaf(v, v, q);
    }
    __shared__ float sh_s[8][OUTF];
    __shared__ float sh_q[8][OUTF];
    sh_s[rsub][col] = s;
    sh_q[rsub][col] = q;
    __syncthreads();
    if (threadIdx.x < OUTF) {
        float ts = 0.f, tq = 0.f;
        #pragma unroll
        for (int r = 0; r < 8; r++) { ts += sh_s[r][threadIdx.x]; tq += sh_q[r][threadIdx.x]; }
        atomicAdd(&g_stats[threadIdx.x], ts);
        atomicAdd(&g_stats[OUTF + threadIdx.x], tq);
    }
}

// ---------------------------------------------------------------------------
// Kernel D: batchnorm (biased variance) into d_out.
__global__ void norm_kernel(const float* __restrict__ gamma,
                            const float* __restrict__ beta,
                            float* __restrict__ out) {
    int idx = blockIdx.x * blockDim.x + threadIdx.x;
    if (idx >= NN * OUTF) return;
    int col = idx % OUTF;
    const float invN = 1.0f / (float)NN;
    float mean = g_stats[col] * invN;
    float var  = fmaf(-mean, mean, g_stats[OUTF + col] * invN);
    float scale = rsqrtf(var + EPS) * gamma[col];
    out[idx] = fmaf(g_pre[idx] - mean, scale, beta[col]);
}

// ---------------------------------------------------------------------------
extern "C" void kernel_launch(void* const* d_in, const int* in_sizes, int n_in,
                              void* d_out, int out_size) {
    const float* x     = (const float*)d_in[0];
    const void*  ei    = d_in[1];               // int64 or int32 [2, E]
    const float* ea    = (const float*)d_in[2];
    const float* nn_w  = (const float*)d_in[3]; // [1, 756]
    const float* nn_b  = (const float*)d_in[4]; // [756]
    const float* root  = (const float*)d_in[5]; // [9, 84]
    const float* bias  = (const float*)d_in[6]; // [84]
    const float* gamma = (const float*)d_in[7];
    const float* beta  = (const float*)d_in[8];
    float* out = (float*)d_out;

    detect_kernel<<<1, 32>>>((const int*)ei);

    {
        int total = NN * OUTF;
        prep_kernel<<<(total + 255) / 256, 256>>>(x, nn_w, nn_b, root, bias);
    }
    {
        long long total = (long long)EE * CH4;
        int blocks = (int)((total + 255) / 256);
        edge_kernel<<<blocks, 256>>>(ei, ea);
    }
    stats_kernel<<<296, 672>>>();
    {
        int total = NN * OUTF;
        norm_kernel<<<(total + 255) / 256, 256>>>(gamma, beta, out);
    }
}